// round 2
// baseline (speedup 1.0000x reference)
#include <cuda_runtime.h>

#define NB 2
#define HH 512
#define WW 512
#define CVH 511
#define CHW 511
#define LL 0.24f
#define NSTEPS 250
#define ROWS_PER_CTA 4

// ---------------- device global scratch (no allocations allowed) -------------
__device__ float g_buf0[NB * HH * WW];
__device__ float g_buf1[NB * HH * WW];
__device__ float g_cv[NB * CVH * WW];      // vertical conductance  (511 x 512)
__device__ float g_ch[NB * HH * CHW];      // horizontal conductance (512 x 511)
__device__ unsigned char g_ur[NB * CVH * CHW];
__device__ unsigned int g_minbits;
__device__ float g_shift;

// ---------------- shift = (min(initial) <= 0.1) ? 0.1 : 0 -------------------
__global__ void k_init() { g_minbits = 0x7f800000u; }

__global__ void k_min(const float* __restrict__ init, int n) {
    float m = 3.4e38f;
    for (int i = blockIdx.x * blockDim.x + threadIdx.x; i < n;
         i += gridDim.x * blockDim.x)
        m = fminf(m, init[i]);
#pragma unroll
    for (int o = 16; o; o >>= 1) m = fminf(m, __shfl_down_sync(0xffffffffu, m, o));
    if ((threadIdx.x & 31) == 0)
        atomicMin(&g_minbits, __float_as_uint(m));  // inputs are >= 0
}

__global__ void k_shift() {
    float mn = __uint_as_float(g_minbits);
    g_shift = (mn <= 0.1f) ? 0.1f : 0.0f;
}

// ------------- cv, ch from guide; depth0 = initial + shift ------------------
__global__ void k_prep(const float* __restrict__ guide,
                       const float* __restrict__ init) {
    int idx = blockIdx.x * blockDim.x + threadIdx.x;
    const int total = NB * HH * WW;
    if (idx >= total) return;
    int b = idx / (HH * WW);
    int rem = idx - b * HH * WW;
    int y = rem / WW, x = rem - y * WW;

    g_buf0[idx] = init[idx] + g_shift;

    const float* gb = guide + b * 3 * HH * WW;
    if (y < CVH) {
        float s = 0.f;
#pragma unroll
        for (int c = 0; c < 3; c++)
            s += fabsf(gb[(c * HH + y + 1) * WW + x] - gb[(c * HH + y) * WW + x]);
        float t = s / 3.0f;
        g_cv[(b * CVH + y) * WW + x] = 1.0f / (1.0f + (t * t) / (0.03f * 0.03f));
    }
    if (x < CHW) {
        float s = 0.f;
#pragma unroll
        for (int c = 0; c < 3; c++)
            s += fabsf(gb[(c * HH + y) * WW + x + 1] - gb[(c * HH + y) * WW + x]);
        float t = s / 3.0f;
        g_ch[(b * HH + y) * CHW + x] = 1.0f / (1.0f + (t * t) / (0.03f * 0.03f));
    }
}

// --------------- uniform regions: 3x3 zero-padded variance < 0.1 ------------
__global__ void k_ur() {
    int idx = blockIdx.x * blockDim.x + threadIdx.x;
    const int total = NB * CVH * CHW;
    if (idx >= total) return;
    int b = idx / (CVH * CHW);
    int rem = idx - b * CVH * CHW;
    int yy = rem / CHW, xx = rem - yy * CHW;

    const float* cvb = g_cv + b * CVH * WW;
    float S1 = 0.f, S2 = 0.f;
#pragma unroll
    for (int dy = -1; dy <= 1; dy++) {
        int r = yy + dy;
        if (r < 0 || r >= CVH) continue;
#pragma unroll
        for (int dx = -1; dx <= 1; dx++) {
            int c = xx + dx;
            if (c < 0 || c >= WW) continue;
            float v = cvb[r * WW + c];
            S1 += v; S2 += v * v;
        }
    }
    float cvv = S2 / 9.0f - (S1 / 9.0f) * (S1 / 9.0f);

    const float* chb = g_ch + b * HH * CHW;
    float T1 = 0.f, T2 = 0.f;
#pragma unroll
    for (int dy = -1; dy <= 1; dy++) {
        int r = yy + dy;
        if (r < 0 || r >= HH) continue;
#pragma unroll
        for (int dx = -1; dx <= 1; dx++) {
            int c = xx + dx;
            if (c < 0 || c >= CHW) continue;
            float v = chb[r * CHW + c];
            T1 += v; T2 += v * v;
        }
    }
    float chv = T2 / 9.0f - (T1 / 9.0f) * (T1 / 9.0f);

    g_ur[idx] = (cvv < 0.1f && chv < 0.1f) ? 1 : 0;
}

// ------- tile "FFT" diffuse == 10 periodic explicit-diffusion steps ---------
// One CTA per batch; 25 overlapping tiles processed strictly sequentially.
__global__ void k_tiles() {
    extern __shared__ float sm[];          // up to 128*128 floats
    __shared__ float red[3][32];
    __shared__ float bcast[3];

    int b = blockIdx.x;
    int tid = threadIdx.x;
    float* D = g_buf0 + b * HH * WW;
    const float* CVb = g_cv + b * CVH * WW;
    const float* CHb = g_ch + b * HH * CHW;
    const unsigned char* URb = g_ur + b * CVH * CHW;

    for (int ty = 0; ty < 5; ty++) {
        for (int tx = 0; tx < 5; tx++) {
            int y = ty * 112, x = tx * 112;
            int h = min(128, HH - y), w = min(128, WW - x);
            int urh = min(y + h, CVH) - y;
            int urw = min(x + w, CHW) - x;
            int npix = h * w;

            // region means: cv over (h-1) x w, ch over h x (w-1), ur over urh x urw
            float scv = 0.f, sch = 0.f, sur = 0.f;
            for (int p = tid; p < npix; p += blockDim.x) {
                int i = p / w, j = p - i * w;
                if (i < h - 1) scv += CVb[(y + i) * WW + (x + j)];
                if (j < w - 1) sch += CHb[(y + i) * CHW + (x + j)];
                if (i < urh && j < urw) sur += (float)URb[(y + i) * CHW + (x + j)];
            }
#pragma unroll
            for (int o = 16; o; o >>= 1) {
                scv += __shfl_down_sync(0xffffffffu, scv, o);
                sch += __shfl_down_sync(0xffffffffu, sch, o);
                sur += __shfl_down_sync(0xffffffffu, sur, o);
            }
            int wid = tid >> 5, lid = tid & 31;
            if (lid == 0) { red[0][wid] = scv; red[1][wid] = sch; red[2][wid] = sur; }
            __syncthreads();
            if (tid == 0) {
                float a = 0.f, bb = 0.f, cc = 0.f;
                int nw = blockDim.x >> 5;
                for (int k = 0; k < nw; k++) { a += red[0][k]; bb += red[1][k]; cc += red[2][k]; }
                bcast[0] = a / (float)((h - 1) * w);
                bcast[1] = bb / (float)(h * (w - 1));
                bcast[2] = cc / (float)(urh * urw);
            }
            __syncthreads();
            float cvm = bcast[0], chm = bcast[1], unif = bcast[2];

            if (unif > 0.7f) {   // uniform branch: whole tile updated
                for (int p = tid; p < npix; p += blockDim.x) {
                    int i = p / w, j = p - i * w;
                    sm[p] = D[(y + i) * WW + (x + j)];
                }
                __syncthreads();
                float acv = LL * cvm, ach = LL * chm;
                float nv[16];
                for (int s = 0; s < 10; s++) {
                    int cnt = 0;
                    for (int p = tid; p < npix; p += blockDim.x) {
                        int i = p / w, j = p - i * w;
                        float c = sm[p];
                        float up = sm[(i == 0 ? h - 1 : i - 1) * w + j];
                        float dn = sm[(i == h - 1 ? 0 : i + 1) * w + j];
                        float lf = sm[i * w + (j == 0 ? w - 1 : j - 1)];
                        float rt = sm[i * w + (j == w - 1 ? 0 : j + 1)];
                        nv[cnt++] = c + acv * (up + dn - 2.0f * c)
                                      + ach * (lf + rt - 2.0f * c);
                    }
                    __syncthreads();
                    cnt = 0;
                    for (int p = tid; p < npix; p += blockDim.x) sm[p] = nv[cnt++];
                    __syncthreads();
                }
                // blend with old (still in global) + writeback
                for (int p = tid; p < npix; p += blockDim.x) {
                    int i = p / w, j = p - i * w;
                    float by = (y > 0) ? ((i < 16) ? (float)i * (1.0f / 16.0f) : 1.0f) : 1.0f;
                    float bx = (x > 0) ? ((j < 16) ? (float)j * (1.0f / 16.0f) : 1.0f) : 1.0f;
                    float bl = by * bx;
                    int g = (y + i) * WW + (x + j);
                    float old = D[g];
                    D[g] = old * (1.0f - bl) + sm[p] * bl;
                }
            }
            __syncthreads();  // make global writes visible before next tile
        }
    }
}

// ------------- one full diffusion step: vertical then horizontal ------------
__global__ void k_step(int parity) {
    const float* src = parity ? g_buf1 : g_buf0;
    float* dst = parity ? g_buf0 : g_buf1;

    __shared__ float smrow[WW];
    int rowbase = blockIdx.x * ROWS_PER_CTA;
    int b = rowbase / HH;
    int y0 = rowbase % HH;
    int x = threadIdx.x;

    const float* I = src + b * HH * WW;
    float* O = dst + b * HH * WW;
    const float* CVb = g_cv + b * CVH * WW;
    const float* CHb = g_ch + b * HH * CHW;

    float Im = (y0 > 0) ? I[(y0 - 1) * WW + x] : 0.0f;
    float Ic = I[y0 * WW + x];
    float cvprev = (y0 > 0) ? CVb[(y0 - 1) * WW + x] : 0.0f;

#pragma unroll
    for (int r = 0; r < ROWS_PER_CTA; r++) {
        int y = y0 + r;
        float Ip = (y < HH - 1) ? I[(y + 1) * WW + x] : 0.0f;
        float cva = (y < CVH) ? CVb[y * WW + x] : 0.0f;
        float tvp = (LL * cvprev) * (Ic - Im);
        float tvc = (LL * cva) * (Ip - Ic);
        float M = (Ic - tvp) + tvc;
        smrow[x] = M;
        __syncthreads();
        float cr = (x < CHW) ? CHb[y * CHW + x] : 0.0f;
        float cl = (x > 0) ? CHb[y * CHW + x - 1] : 0.0f;
        float Ml = (x > 0) ? smrow[x - 1] : 0.0f;
        float Mr = (x < WW - 1) ? smrow[x + 1] : 0.0f;
        float thp = (LL * cl) * (M - Ml);
        float thc = (LL * cr) * (Mr - M);
        O[y * WW + x] = (M - thp) + thc;
        __syncthreads();
        Im = Ic; Ic = Ip; cvprev = cva;
    }
}

// --------------------------- final: out = buf0 - shift ----------------------
__global__ void k_final(float* __restrict__ out, int n) {
    int i = blockIdx.x * blockDim.x + threadIdx.x;
    if (i < n) out[i] = g_buf0[i] - g_shift;
}

// ----------------------------------------------------------------------------
extern "C" void kernel_launch(void* const* d_in, const int* in_sizes, int n_in,
                              void* d_out, int out_size) {
    const float* guide;
    const float* initial;
    if (in_sizes[0] == NB * 3 * HH * WW) {
        guide = (const float*)d_in[0];
        initial = (const float*)d_in[1];
    } else {
        guide = (const float*)d_in[1];
        initial = (const float*)d_in[0];
    }
    float* out = (float*)d_out;
    const int n = NB * HH * WW;

    cudaFuncSetAttribute(k_tiles, cudaFuncAttributeMaxDynamicSharedMemorySize,
                         128 * 128 * 4);

    k_init<<<1, 1>>>();
    k_min<<<256, 256>>>(initial, n);
    k_shift<<<1, 1>>>();
    k_prep<<<(n + 255) / 256, 256>>>(guide, initial);
    k_ur<<<(NB * CVH * CHW + 255) / 256, 256>>>();
    k_tiles<<<2, 1024, 128 * 128 * 4>>>();
    for (int s = 0; s < NSTEPS; s++)
        k_step<<<(NB * HH) / ROWS_PER_CTA, WW>>>(s & 1);
    k_final<<<(n + 255) / 256, 256>>>(out, n);
}

// round 5
// speedup vs baseline: 1.1747x; 1.1747x over previous
#include <cuda_runtime.h>

#define NB 2
#define HH 512
#define WW 512
#define CVH 511
#define CHW 511
#define LL 0.24f
#define NSTEPS 250

#define K_FUSE 5
#define R_ROWS 8
#define WIN (R_ROWS + 2 * K_FUSE)          // 18
#define CTAS_PER_IMG (HH / R_ROWS)         // 64
#define NSUPER (NSTEPS / K_FUSE)           // 50

// ---------------- device global scratch (no allocations allowed) -------------
__device__ float g_buf0[NB * HH * WW];
__device__ float g_buf1[NB * HH * WW];
__device__ float g_cv[NB * CVH * WW];      // vertical conductance  (511 x 512)
__device__ float g_ch[NB * HH * CHW];      // horizontal conductance (512 x 511)
__device__ unsigned char g_ur[NB * CVH * CHW];
__device__ unsigned int g_minbits;
__device__ float g_shift;

// ---------------- shift = (min(initial) <= 0.1) ? 0.1 : 0 -------------------
__global__ void k_init() { g_minbits = 0x7f800000u; }

__global__ void k_min(const float* __restrict__ init, int n) {
    float m = 3.4e38f;
    for (int i = blockIdx.x * blockDim.x + threadIdx.x; i < n;
         i += gridDim.x * blockDim.x)
        m = fminf(m, init[i]);
#pragma unroll
    for (int o = 16; o; o >>= 1) m = fminf(m, __shfl_down_sync(0xffffffffu, m, o));
    if ((threadIdx.x & 31) == 0)
        atomicMin(&g_minbits, __float_as_uint(m));  // inputs are >= 0
}

__global__ void k_shift() {
    float mn = __uint_as_float(g_minbits);
    g_shift = (mn <= 0.1f) ? 0.1f : 0.0f;
}

// ------------- cv, ch from guide; depth0 = initial + shift ------------------
__global__ void k_prep(const float* __restrict__ guide,
                       const float* __restrict__ init) {
    int idx = blockIdx.x * blockDim.x + threadIdx.x;
    const int total = NB * HH * WW;
    if (idx >= total) return;
    int b = idx / (HH * WW);
    int rem = idx - b * HH * WW;
    int y = rem / WW, x = rem - y * WW;

    g_buf0[idx] = init[idx] + g_shift;

    const float* gb = guide + b * 3 * HH * WW;
    if (y < CVH) {
        float s = 0.f;
#pragma unroll
        for (int c = 0; c < 3; c++)
            s += fabsf(gb[(c * HH + y + 1) * WW + x] - gb[(c * HH + y) * WW + x]);
        float t = s / 3.0f;
        g_cv[(b * CVH + y) * WW + x] = 1.0f / (1.0f + (t * t) / (0.03f * 0.03f));
    }
    if (x < CHW) {
        float s = 0.f;
#pragma unroll
        for (int c = 0; c < 3; c++)
            s += fabsf(gb[(c * HH + y) * WW + x + 1] - gb[(c * HH + y) * WW + x]);
        float t = s / 3.0f;
        g_ch[(b * HH + y) * CHW + x] = 1.0f / (1.0f + (t * t) / (0.03f * 0.03f));
    }
}

// --------------- uniform regions: 3x3 zero-padded variance < 0.1 ------------
__global__ void k_ur() {
    int idx = blockIdx.x * blockDim.x + threadIdx.x;
    const int total = NB * CVH * CHW;
    if (idx >= total) return;
    int b = idx / (CVH * CHW);
    int rem = idx - b * CVH * CHW;
    int yy = rem / CHW, xx = rem - yy * CHW;

    const float* cvb = g_cv + b * CVH * WW;
    float S1 = 0.f, S2 = 0.f;
#pragma unroll
    for (int dy = -1; dy <= 1; dy++) {
        int r = yy + dy;
        if (r < 0 || r >= CVH) continue;
#pragma unroll
        for (int dx = -1; dx <= 1; dx++) {
            int c = xx + dx;
            if (c < 0 || c >= WW) continue;
            float v = cvb[r * WW + c];
            S1 += v; S2 += v * v;
        }
    }
    float cvv = S2 / 9.0f - (S1 / 9.0f) * (S1 / 9.0f);

    const float* chb = g_ch + b * HH * CHW;
    float T1 = 0.f, T2 = 0.f;
#pragma unroll
    for (int dy = -1; dy <= 1; dy++) {
        int r = yy + dy;
        if (r < 0 || r >= HH) continue;
#pragma unroll
        for (int dx = -1; dx <= 1; dx++) {
            int c = xx + dx;
            if (c < 0 || c >= CHW) continue;
            float v = chb[r * CHW + c];
            T1 += v; T2 += v * v;
        }
    }
    float chv = T2 / 9.0f - (T1 / 9.0f) * (T1 / 9.0f);

    g_ur[idx] = (cvv < 0.1f && chv < 0.1f) ? 1 : 0;
}

// ------- tile "FFT" diffuse == 10 periodic explicit-diffusion steps ---------
__global__ void k_tiles() {
    extern __shared__ float sm[];
    __shared__ float red[3][32];
    __shared__ float bcast[3];

    int b = blockIdx.x;
    int tid = threadIdx.x;
    float* D = g_buf0 + b * HH * WW;
    const float* CVb = g_cv + b * CVH * WW;
    const float* CHb = g_ch + b * HH * CHW;
    const unsigned char* URb = g_ur + b * CVH * CHW;

    for (int ty = 0; ty < 5; ty++) {
        for (int tx = 0; tx < 5; tx++) {
            int y = ty * 112, x = tx * 112;
            int h = min(128, HH - y), w = min(128, WW - x);
            int urh = min(y + h, CVH) - y;
            int urw = min(x + w, CHW) - x;
            int npix = h * w;

            float scv = 0.f, sch = 0.f, sur = 0.f;
            for (int p = tid; p < npix; p += blockDim.x) {
                int i = p / w, j = p - i * w;
                if (i < h - 1) scv += CVb[(y + i) * WW + (x + j)];
                if (j < w - 1) sch += CHb[(y + i) * CHW + (x + j)];
                if (i < urh && j < urw) sur += (float)URb[(y + i) * CHW + (x + j)];
            }
#pragma unroll
            for (int o = 16; o; o >>= 1) {
                scv += __shfl_down_sync(0xffffffffu, scv, o);
                sch += __shfl_down_sync(0xffffffffu, sch, o);
                sur += __shfl_down_sync(0xffffffffu, sur, o);
            }
            int wid = tid >> 5, lid = tid & 31;
            if (lid == 0) { red[0][wid] = scv; red[1][wid] = sch; red[2][wid] = sur; }
            __syncthreads();
            if (tid == 0) {
                float a = 0.f, bb = 0.f, cc = 0.f;
                int nw = blockDim.x >> 5;
                for (int k = 0; k < nw; k++) { a += red[0][k]; bb += red[1][k]; cc += red[2][k]; }
                bcast[0] = a / (float)((h - 1) * w);
                bcast[1] = bb / (float)(h * (w - 1));
                bcast[2] = cc / (float)(urh * urw);
            }
            __syncthreads();
            float cvm = bcast[0], chm = bcast[1], unif = bcast[2];

            if (unif > 0.7f) {
                for (int p = tid; p < npix; p += blockDim.x) {
                    int i = p / w, j = p - i * w;
                    sm[p] = D[(y + i) * WW + (x + j)];
                }
                __syncthreads();
                float acv = LL * cvm, ach = LL * chm;
                float nv[16];
                for (int s = 0; s < 10; s++) {
                    int cnt = 0;
                    for (int p = tid; p < npix; p += blockDim.x) {
                        int i = p / w, j = p - i * w;
                        float c = sm[p];
                        float up = sm[(i == 0 ? h - 1 : i - 1) * w + j];
                        float dn = sm[(i == h - 1 ? 0 : i + 1) * w + j];
                        float lf = sm[i * w + (j == 0 ? w - 1 : j - 1)];
                        float rt = sm[i * w + (j == w - 1 ? 0 : j + 1)];
                        nv[cnt++] = c + acv * (up + dn - 2.0f * c)
                                      + ach * (lf + rt - 2.0f * c);
                    }
                    __syncthreads();
                    cnt = 0;
                    for (int p = tid; p < npix; p += blockDim.x) sm[p] = nv[cnt++];
                    __syncthreads();
                }
                for (int p = tid; p < npix; p += blockDim.x) {
                    int i = p / w, j = p - i * w;
                    float by = (y > 0) ? ((i < 16) ? (float)i * (1.0f / 16.0f) : 1.0f) : 1.0f;
                    float bx = (x > 0) ? ((j < 16) ? (float)j * (1.0f / 16.0f) : 1.0f) : 1.0f;
                    float bl = by * bx;
                    int g = (y + i) * WW + (x + j);
                    float old = D[g];
                    D[g] = old * (1.0f - bl) + sm[p] * bl;
                }
            }
            __syncthreads();
        }
    }
}

// -------- fused K_FUSE diffusion steps with halo redundancy -----------------
// Thread = column. Vertical pass register-local; horizontal via one smem stage.
// Bit-exact vs sequential stepping: valid window shrinks 1 row/side per step.
__global__ void __launch_bounds__(WW, 1) k_fused(int parity) {
    const float* src = parity ? g_buf1 : g_buf0;
    float* dst = parity ? g_buf0 : g_buf1;

    int cta = blockIdx.x;
    int b = cta / CTAS_PER_IMG;
    int y0 = (cta - b * CTAS_PER_IMG) * R_ROWS;
    int x = threadIdx.x;
    int ybase = y0 - K_FUSE;

    const float* I = src + b * HH * WW;
    float* O = dst + b * HH * WW;
    const float* CVb = g_cv + b * CVH * WW;
    const float* CHb = g_ch + b * HH * CHW;

    float S[WIN], CVr[WIN], CHr[WIN];
#pragma unroll
    for (int j = 0; j < WIN; j++) {
        int y = ybase + j;
        bool iny = (y >= 0 && y < HH);
        S[j]   = iny ? I[y * WW + x] : 0.0f;
        CVr[j] = (y >= 0 && y < CVH) ? CVb[y * WW + x] : 0.0f;     // gates (y, y+1)
        CHr[j] = (iny && x < CHW) ? CHb[y * CHW + x] : 0.0f;       // gates (x, x+1)
    }

    __shared__ float smM[WIN][WW + 1];

#pragma unroll
    for (int s = 0; s < K_FUSE; s++) {
        int lo = max(0, y0 - K_FUSE + s + 1);               // image rows updated
        int hi = min(HH - 1, y0 + R_ROWS - 1 + K_FUSE - s - 1);

        // vertical pass (register-local per column) -> stage M in smem
#pragma unroll
        for (int j = 1; j < WIN - 1; j++) {
            int y = ybase + j;
            if (y >= lo && y <= hi) {
                float tvp = (LL * CVr[j - 1]) * (S[j] - S[j - 1]);  // cv[y-1]
                float tvc = (LL * CVr[j]) * (S[j + 1] - S[j]);      // cv[y]
                smM[j][x] = (S[j] - tvp) + tvc;
            }
        }
        __syncthreads();

        // horizontal pass
#pragma unroll
        for (int j = 1; j < WIN - 1; j++) {
            int y = ybase + j;
            if (y >= lo && y <= hi) {                  // uniform across block
                float Mc = smM[j][x];
                float Ml = (x > 0) ? smM[j][x - 1] : 0.0f;
                float Mr = (x < WW - 1) ? smM[j][x + 1] : 0.0f;
                float chl = __shfl_up_sync(0xffffffffu, CHr[j], 1);
                if ((x & 31) == 0) chl = (x > 0) ? CHb[y * CHW + x - 1] : 0.0f;
                float chr = CHr[j];                    // 0 at x = WW-1 by load
                float thp = (LL * chl) * (Mc - Ml);
                float thc = (LL * chr) * (Mr - Mc);
                S[j] = (Mc - thp) + thc;
            }
        }
        __syncthreads();
    }

#pragma unroll
    for (int j = K_FUSE; j < K_FUSE + R_ROWS; j++)
        O[(ybase + j) * WW + x] = S[j];
}

// --------------------------- final: out = buf0 - shift ----------------------
__global__ void k_final(float* __restrict__ out, int n) {
    int i = blockIdx.x * blockDim.x + threadIdx.x;
    if (i < n) out[i] = g_buf0[i] - g_shift;
}

// ----------------------------------------------------------------------------
extern "C" void kernel_launch(void* const* d_in, const int* in_sizes, int n_in,
                              void* d_out, int out_size) {
    const float* guide;
    const float* initial;
    if (in_sizes[0] == NB * 3 * HH * WW) {
        guide = (const float*)d_in[0];
        initial = (const float*)d_in[1];
    } else {
        guide = (const float*)d_in[1];
        initial = (const float*)d_in[0];
    }
    float* out = (float*)d_out;
    const int n = NB * HH * WW;

    cudaFuncSetAttribute(k_tiles, cudaFuncAttributeMaxDynamicSharedMemorySize,
                         128 * 128 * 4);

    k_init<<<1, 1>>>();
    k_min<<<256, 256>>>(initial, n);
    k_shift<<<1, 1>>>();
    k_prep<<<(n + 255) / 256, 256>>>(guide, initial);
    k_ur<<<(NB * CVH * CHW + 255) / 256, 256>>>();
    k_tiles<<<2, 1024, 128 * 128 * 4>>>();
    for (int s = 0; s < NSUPER; s++)
        k_fused<<<NB * CTAS_PER_IMG, WW>>>(s & 1);
    k_final<<<(n + 255) / 256, 256>>>(out, n);
}

// round 7
// speedup vs baseline: 2.5086x; 2.1356x over previous
#include <cuda_runtime.h>

#define NB 2
#define HH 512
#define WW 512
#define CVH 511
#define CHW 511
#define LL 0.24f
#define NSTEPS 250

#define K_FUSE 5
#define R_ROWS 8
#define WIN (R_ROWS + 2 * K_FUSE)          // 18
#define CTAS_PER_IMG (HH / R_ROWS)         // 64
#define NSUPER (NSTEPS / K_FUSE)           // 50

// ---------------- device global scratch (no allocations allowed) -------------
__device__ float g_buf0[NB * HH * WW];
__device__ float g_buf1[NB * HH * WW];
__device__ float g_cv[NB * CVH * WW];      // vertical conductance  (511 x 512)
__device__ float g_ch[NB * HH * CHW];      // horizontal conductance (512 x 511)
__device__ unsigned char g_ur[NB * CVH * CHW];
__device__ unsigned int g_minbits;
__device__ float g_shift;

// ---------------- shift = (min(initial) <= 0.1) ? 0.1 : 0 -------------------
__global__ void k_init() { g_minbits = 0x7f800000u; }

__global__ void k_min(const float* __restrict__ init, int n) {
    float m = 3.4e38f;
    for (int i = blockIdx.x * blockDim.x + threadIdx.x; i < n;
         i += gridDim.x * blockDim.x)
        m = fminf(m, init[i]);
#pragma unroll
    for (int o = 16; o; o >>= 1) m = fminf(m, __shfl_down_sync(0xffffffffu, m, o));
    if ((threadIdx.x & 31) == 0)
        atomicMin(&g_minbits, __float_as_uint(m));  // inputs are >= 0
}

__global__ void k_shift() {
    float mn = __uint_as_float(g_minbits);
    g_shift = (mn <= 0.1f) ? 0.1f : 0.0f;
}

// ------------- cv, ch from guide; depth0 = initial + shift ------------------
__global__ void k_prep(const float* __restrict__ guide,
                       const float* __restrict__ init) {
    int idx = blockIdx.x * blockDim.x + threadIdx.x;
    const int total = NB * HH * WW;
    if (idx >= total) return;
    int b = idx / (HH * WW);
    int rem = idx - b * HH * WW;
    int y = rem / WW, x = rem - y * WW;

    g_buf0[idx] = init[idx] + g_shift;

    const float* gb = guide + b * 3 * HH * WW;
    if (y < CVH) {
        float s = 0.f;
#pragma unroll
        for (int c = 0; c < 3; c++)
            s += fabsf(gb[(c * HH + y + 1) * WW + x] - gb[(c * HH + y) * WW + x]);
        float t = s / 3.0f;
        g_cv[(b * CVH + y) * WW + x] = 1.0f / (1.0f + (t * t) / (0.03f * 0.03f));
    }
    if (x < CHW) {
        float s = 0.f;
#pragma unroll
        for (int c = 0; c < 3; c++)
            s += fabsf(gb[(c * HH + y) * WW + x + 1] - gb[(c * HH + y) * WW + x]);
        float t = s / 3.0f;
        g_ch[(b * HH + y) * CHW + x] = 1.0f / (1.0f + (t * t) / (0.03f * 0.03f));
    }
}

// --------------- uniform regions: 3x3 zero-padded variance < 0.1 ------------
__global__ void k_ur() {
    int idx = blockIdx.x * blockDim.x + threadIdx.x;
    const int total = NB * CVH * CHW;
    if (idx >= total) return;
    int b = idx / (CVH * CHW);
    int rem = idx - b * CVH * CHW;
    int yy = rem / CHW, xx = rem - yy * CHW;

    const float* cvb = g_cv + b * CVH * WW;
    float S1 = 0.f, S2 = 0.f;
#pragma unroll
    for (int dy = -1; dy <= 1; dy++) {
        int r = yy + dy;
        if (r < 0 || r >= CVH) continue;
#pragma unroll
        for (int dx = -1; dx <= 1; dx++) {
            int c = xx + dx;
            if (c < 0 || c >= WW) continue;
            float v = cvb[r * WW + c];
            S1 += v; S2 += v * v;
        }
    }
    float cvv = S2 / 9.0f - (S1 / 9.0f) * (S1 / 9.0f);

    const float* chb = g_ch + b * HH * CHW;
    float T1 = 0.f, T2 = 0.f;
#pragma unroll
    for (int dy = -1; dy <= 1; dy++) {
        int r = yy + dy;
        if (r < 0 || r >= HH) continue;
#pragma unroll
        for (int dx = -1; dx <= 1; dx++) {
            int c = xx + dx;
            if (c < 0 || c >= CHW) continue;
            float v = chb[r * CHW + c];
            T1 += v; T2 += v * v;
        }
    }
    float chv = T2 / 9.0f - (T1 / 9.0f) * (T1 / 9.0f);

    g_ur[idx] = (cvv < 0.1f && chv < 0.1f) ? 1 : 0;
}

// ---- templated tile body: load -> 10 periodic stencil steps -> blend -------
// Static thread->pixel mapping: x = tid % W, rows strided by GROUPS = 1024/W.
// Fully unrolled; nv[] in registers; same arithmetic as the reference order.
template <int H, int W>
__device__ __forceinline__ void tile_body(float* __restrict__ sm,
                                          float* __restrict__ D,
                                          int y0g, int x0g,
                                          float acv, float ach, int tid) {
    constexpr int GROUPS = 1024 / W;       // row groups processed per pass
    constexpr int NPIX = (H * W) / 1024;   // pixels per thread
    const int x = tid & (W - 1);
    const int yb = tid / W;                // 0..GROUPS-1

    // load tile into smem (coalesced: x contiguous in warp)
#pragma unroll
    for (int k = 0; k < NPIX; k++) {
        int i = yb + k * GROUPS;
        sm[i * W + x] = D[(y0g + i) * WW + (x0g + x)];
    }
    __syncthreads();

    float nv[NPIX];
#pragma unroll 1
    for (int s = 0; s < 10; s++) {
#pragma unroll
        for (int k = 0; k < NPIX; k++) {
            int i = yb + k * GROUPS;
            float c = sm[i * W + x];
            float up = sm[((i == 0) ? H - 1 : i - 1) * W + x];
            float dn = sm[((i == H - 1) ? 0 : i + 1) * W + x];
            float lf = sm[i * W + ((x == 0) ? W - 1 : x - 1)];
            float rt = sm[i * W + ((x == W - 1) ? 0 : x + 1)];
            nv[k] = c + acv * (up + dn - 2.0f * c)
                      + ach * (lf + rt - 2.0f * c);
        }
        __syncthreads();
#pragma unroll
        for (int k = 0; k < NPIX; k++)
            sm[(yb + k * GROUPS) * W + x] = nv[k];
        __syncthreads();
    }

    // blend with old global values + writeback
#pragma unroll
    for (int k = 0; k < NPIX; k++) {
        int i = yb + k * GROUPS;
        float by = (y0g > 0) ? ((i < 16) ? (float)i * (1.0f / 16.0f) : 1.0f) : 1.0f;
        float bx = (x0g > 0) ? ((x < 16) ? (float)x * (1.0f / 16.0f) : 1.0f) : 1.0f;
        float bl = by * bx;
        int g = (y0g + i) * WW + (x0g + x);
        float old = D[g];
        D[g] = old * (1.0f - bl) + sm[i * W + x] * bl;
    }
}

// ------- tile "FFT" diffuse == 10 periodic explicit-diffusion steps ---------
__global__ void __launch_bounds__(1024, 1) k_tiles() {
    extern __shared__ float sm[];
    __shared__ float red[3][32];
    __shared__ float bcast[3];

    int b = blockIdx.x;
    int tid = threadIdx.x;
    float* D = g_buf0 + b * HH * WW;
    const float* CVb = g_cv + b * CVH * WW;
    const float* CHb = g_ch + b * HH * CHW;
    const unsigned char* URb = g_ur + b * CVH * CHW;

    for (int ty = 0; ty < 5; ty++) {
        for (int tx = 0; tx < 5; tx++) {
            int y = ty * 112, x = tx * 112;
            int h = min(128, HH - y), w = min(128, WW - x);
            int urh = min(y + h, CVH) - y;
            int urw = min(x + w, CHW) - x;
            int npix = h * w;

            float scv = 0.f, sch = 0.f, sur = 0.f;
            for (int p = tid; p < npix; p += blockDim.x) {
                int i = p / w, j = p - i * w;
                if (i < h - 1) scv += CVb[(y + i) * WW + (x + j)];
                if (j < w - 1) sch += CHb[(y + i) * CHW + (x + j)];
                if (i < urh && j < urw) sur += (float)URb[(y + i) * CHW + (x + j)];
            }
#pragma unroll
            for (int o = 16; o; o >>= 1) {
                scv += __shfl_down_sync(0xffffffffu, scv, o);
                sch += __shfl_down_sync(0xffffffffu, sch, o);
                sur += __shfl_down_sync(0xffffffffu, sur, o);
            }
            int wid = tid >> 5, lid = tid & 31;
            if (lid == 0) { red[0][wid] = scv; red[1][wid] = sch; red[2][wid] = sur; }
            __syncthreads();
            if (tid == 0) {
                float a = 0.f, bb = 0.f, cc = 0.f;
                int nw = blockDim.x >> 5;
                for (int k = 0; k < nw; k++) { a += red[0][k]; bb += red[1][k]; cc += red[2][k]; }
                bcast[0] = a / (float)((h - 1) * w);
                bcast[1] = bb / (float)(h * (w - 1));
                bcast[2] = cc / (float)(urh * urw);
            }
            __syncthreads();
            float cvm = bcast[0], chm = bcast[1], unif = bcast[2];

            if (unif > 0.7f) {
                float acv = LL * cvm, ach = LL * chm;
                if (h == 128) {
                    if (w == 128) tile_body<128, 128>(sm, D, y, x, acv, ach, tid);
                    else          tile_body<128, 64>(sm, D, y, x, acv, ach, tid);
                } else {
                    if (w == 128) tile_body<64, 128>(sm, D, y, x, acv, ach, tid);
                    else          tile_body<64, 64>(sm, D, y, x, acv, ach, tid);
                }
            }
            __syncthreads();
        }
    }
}

// -------- fused K_FUSE diffusion steps with halo redundancy -----------------
__global__ void __launch_bounds__(WW, 1) k_fused(int parity) {
    const float* src = parity ? g_buf1 : g_buf0;
    float* dst = parity ? g_buf0 : g_buf1;

    int cta = blockIdx.x;
    int b = cta / CTAS_PER_IMG;
    int y0 = (cta - b * CTAS_PER_IMG) * R_ROWS;
    int x = threadIdx.x;
    int ybase = y0 - K_FUSE;

    const float* I = src + b * HH * WW;
    float* O = dst + b * HH * WW;
    const float* CVb = g_cv + b * CVH * WW;
    const float* CHb = g_ch + b * HH * CHW;

    float S[WIN], CVr[WIN], CHr[WIN];
#pragma unroll
    for (int j = 0; j < WIN; j++) {
        int y = ybase + j;
        bool iny = (y >= 0 && y < HH);
        S[j]   = iny ? I[y * WW + x] : 0.0f;
        CVr[j] = (y >= 0 && y < CVH) ? CVb[y * WW + x] : 0.0f;
        CHr[j] = (iny && x < CHW) ? CHb[y * CHW + x] : 0.0f;
    }

    __shared__ float smM[WIN][WW + 1];

#pragma unroll
    for (int s = 0; s < K_FUSE; s++) {
        int lo = max(0, y0 - K_FUSE + s + 1);
        int hi = min(HH - 1, y0 + R_ROWS - 1 + K_FUSE - s - 1);

#pragma unroll
        for (int j = 1; j < WIN - 1; j++) {
            int y = ybase + j;
            if (y >= lo && y <= hi) {
                float tvp = (LL * CVr[j - 1]) * (S[j] - S[j - 1]);
                float tvc = (LL * CVr[j]) * (S[j + 1] - S[j]);
                smM[j][x] = (S[j] - tvp) + tvc;
            }
        }
        __syncthreads();

#pragma unroll
        for (int j = 1; j < WIN - 1; j++) {
            int y = ybase + j;
            if (y >= lo && y <= hi) {
                float Mc = smM[j][x];
                float Ml = (x > 0) ? smM[j][x - 1] : 0.0f;
                float Mr = (x < WW - 1) ? smM[j][x + 1] : 0.0f;
                float chl = __shfl_up_sync(0xffffffffu, CHr[j], 1);
                if ((x & 31) == 0) chl = (x > 0) ? CHb[y * CHW + x - 1] : 0.0f;
                float chr = CHr[j];
                float thp = (LL * chl) * (Mc - Ml);
                float thc = (LL * chr) * (Mr - Mc);
                S[j] = (Mc - thp) + thc;
            }
        }
        __syncthreads();
    }

#pragma unroll
    for (int j = K_FUSE; j < K_FUSE + R_ROWS; j++)
        O[(ybase + j) * WW + x] = S[j];
}

// --------------------------- final: out = buf0 - shift ----------------------
__global__ void k_final(float* __restrict__ out, int n) {
    int i = blockIdx.x * blockDim.x + threadIdx.x;
    if (i < n) out[i] = g_buf0[i] - g_shift;
}

// ----------------------------------------------------------------------------
extern "C" void kernel_launch(void* const* d_in, const int* in_sizes, int n_in,
                              void* d_out, int out_size) {
    const float* guide;
    const float* initial;
    if (in_sizes[0] == NB * 3 * HH * WW) {
        guide = (const float*)d_in[0];
        initial = (const float*)d_in[1];
    } else {
        guide = (const float*)d_in[1];
        initial = (const float*)d_in[0];
    }
    float* out = (float*)d_out;
    const int n = NB * HH * WW;

    cudaFuncSetAttribute(k_tiles, cudaFuncAttributeMaxDynamicSharedMemorySize,
                         128 * 128 * 4);

    k_init<<<1, 1>>>();
    k_min<<<256, 256>>>(initial, n);
    k_shift<<<1, 1>>>();
    k_prep<<<(n + 255) / 256, 256>>>(guide, initial);
    k_ur<<<(NB * CVH * CHW + 255) / 256, 256>>>();
    k_tiles<<<2, 1024, 128 * 128 * 4>>>();
    for (int s = 0; s < NSUPER; s++)
        k_fused<<<NB * CTAS_PER_IMG, WW>>>(s & 1);
    k_final<<<(n + 255) / 256, 256>>>(out, n);
}